// round 3
// baseline (speedup 1.0000x reference)
#include <cuda_runtime.h>

typedef unsigned long long ull;

#define NN 50000
#define DD 128
#define EE 1600000
#define TWO_N (2*NN)
#define SCAN_B 512
#define NSB ((TWO_N + SCAN_B - 1)/SCAN_B)
#define TILE_R 64
#define NBLK ((NN + TILE_R - 1)/TILE_R)
#define PAD 68     // transposed tile pad (words), multiple of 4 for b64x2 loads
#define RMP 132    // row-major pad

// ---------------- f32x2 packed-math helpers ----------------
__device__ __forceinline__ ull bcast2(float x) {
    ull r; asm("mov.b64 %0, {%1,%1};" : "=l"(r) : "f"(x)); return r;
}
__device__ __forceinline__ ull pack2f(float lo, float hi) {
    ull r; asm("mov.b64 %0, {%1,%2};" : "=l"(r) : "f"(lo), "f"(hi)); return r;
}
__device__ __forceinline__ void ffma2(ull& d, ull a, ull b) {
    asm("fma.rn.f32x2 %0, %1, %2, %0;" : "+l"(d) : "l"(a), "l"(b));
}
__device__ __forceinline__ float2 unpack2(ull v) {
    float2 f; asm("mov.b64 {%0,%1}, %2;" : "=f"(f.x), "=f"(f.y) : "l"(v)); return f;
}

// ---------------- scratch ----------------
__device__ int   g_cnt[TWO_N];
__device__ int   g_off[TWO_N + 1];
__device__ int   g_bsum[NSB];
__device__ int   g_col[2*EE];
__device__ float g_ua[NN*DD];
__device__ float g_ub[NN*DD];

// ---------------- CSR construction ----------------
__global__ void zero_cnt_kernel() {
    int i = blockIdx.x*blockDim.x + threadIdx.x;
    if (i < TWO_N) g_cnt[i] = 0;
}

__global__ void hist_kernel(const int* __restrict__ et, const int* __restrict__ ex) {
    int i = blockIdx.x*blockDim.x + threadIdx.x;
    if (i < EE) {
        atomicAdd(&g_cnt[et[EE + i]], 1);
        atomicAdd(&g_cnt[NN + ex[EE + i]], 1);
    }
}

__global__ void scan1_kernel() {
    __shared__ int s[SCAN_B];
    int i = blockIdx.x*SCAN_B + threadIdx.x;
    int v = (i < TWO_N) ? g_cnt[i] : 0;
    s[threadIdx.x] = v;
    __syncthreads();
    #pragma unroll
    for (int d = 1; d < SCAN_B; d <<= 1) {
        int tv = (threadIdx.x >= d) ? s[threadIdx.x - d] : 0;
        __syncthreads();
        s[threadIdx.x] += tv;
        __syncthreads();
    }
    if (i < TWO_N) g_off[i + 1] = s[threadIdx.x];
    if (threadIdx.x == SCAN_B - 1) g_bsum[blockIdx.x] = s[SCAN_B - 1];
}

__global__ void scan2_kernel() {
    __shared__ int s[256];
    int v = (threadIdx.x < NSB) ? g_bsum[threadIdx.x] : 0;
    s[threadIdx.x] = v;
    __syncthreads();
    #pragma unroll
    for (int d = 1; d < 256; d <<= 1) {
        int tv = (threadIdx.x >= d) ? s[threadIdx.x - d] : 0;
        __syncthreads();
        s[threadIdx.x] += tv;
        __syncthreads();
    }
    if (threadIdx.x < NSB) g_bsum[threadIdx.x] = s[threadIdx.x] - v;
}

__global__ void scan3_kernel() {
    int i = blockIdx.x*blockDim.x + threadIdx.x;
    if (i == 0) { g_off[0] = 0; g_cnt[0] = 0; }
    else if (i <= TWO_N) {
        int v = g_off[i] + g_bsum[(i - 1) / SCAN_B];
        g_off[i] = v;
        if (i < TWO_N) g_cnt[i] = v;
    }
}

__global__ void fill_kernel(const int* __restrict__ et, const int* __restrict__ ex) {
    int i = blockIdx.x*blockDim.x + threadIdx.x;
    if (i < EE) {
        int p = atomicAdd(&g_cnt[et[EE + i]], 1);
        g_col[p] = et[i];
        int q = atomicAdd(&g_cnt[NN + ex[EE + i]], 1);
        g_col[q] = ex[i];
    }
}

// ---------------- aggregation: warp per destination node ----------------
__global__ void agg_kernel(const float* __restrict__ x, const float* __restrict__ t,
                           float* __restrict__ ua, float* __restrict__ ub) {
    int warp = (blockIdx.x*blockDim.x + threadIdx.x) >> 5;
    int lane = threadIdx.x & 31;
    if (warp >= NN) return;
    const float4* t4 = (const float4*)t;
    const float4* x4 = (const float4*)x;

    float4 base = t4[warp*32 + lane];
    float4 aA = base, aB = base;

    int e  = g_off[warp],      eE = g_off[warp + 1];
    for (; e + 1 < eE; e += 2) {
        int s0 = g_col[e], s1 = g_col[e + 1];
        float4 v0 = t4[s0*32 + lane];
        float4 v1 = t4[s1*32 + lane];
        aA.x += v0.x; aA.y += v0.y; aA.z += v0.z; aA.w += v0.w;
        aA.x += v1.x; aA.y += v1.y; aA.z += v1.z; aA.w += v1.w;
    }
    if (e < eE) {
        int s0 = g_col[e];
        float4 v0 = t4[s0*32 + lane];
        aA.x += v0.x; aA.y += v0.y; aA.z += v0.z; aA.w += v0.w;
    }

    e = g_off[NN + warp]; eE = g_off[NN + warp + 1];
    for (; e + 1 < eE; e += 2) {
        int s0 = g_col[e], s1 = g_col[e + 1];
        float4 v0 = x4[s0*32 + lane];
        float4 v1 = x4[s1*32 + lane];
        aB.x += v0.x; aB.y += v0.y; aB.z += v0.z; aB.w += v0.w;
        aB.x += v1.x; aB.y += v1.y; aB.z += v1.z; aB.w += v1.w;
    }
    if (e < eE) {
        int s0 = g_col[e];
        float4 v0 = x4[s0*32 + lane];
        aB.x += v0.x; aB.y += v0.y; aB.z += v0.z; aB.w += v0.w;
    }

    ((float4*)ua)[warp*32 + lane] = aA;
    ((float4*)ub)[warp*32 + lane] = aB;
}

// ================= GEMM building blocks =================
// layer over transposed tile sIn[128][PAD]: b64 pair loads (broadcast, aligned)
__device__ __forceinline__ void gemm_layer_T(const float* __restrict__ sIn,
                                             const float* __restrict__ sW,
                                             int rb, int tc, ull acc[4][4]) {
    #pragma unroll 4
    for (int k = 0; k < 128; k++) {
        ulonglong2 A0 = *(const ulonglong2*)&sIn[k*PAD + rb];
        ulonglong2 A1 = *(const ulonglong2*)&sIn[k*PAD + rb + 4];
        float4 bv = *(const float4*)(sW + k*128 + tc*4);
        ull b0 = bcast2(bv.x), b1 = bcast2(bv.y), b2 = bcast2(bv.z), b3 = bcast2(bv.w);
        ull ap0 = A0.x, ap1 = A0.y, ap2 = A1.x, ap3 = A1.y;
        ffma2(acc[0][0], ap0, b0); ffma2(acc[0][1], ap0, b1); ffma2(acc[0][2], ap0, b2); ffma2(acc[0][3], ap0, b3);
        ffma2(acc[1][0], ap1, b0); ffma2(acc[1][1], ap1, b1); ffma2(acc[1][2], ap1, b2); ffma2(acc[1][3], ap1, b3);
        ffma2(acc[2][0], ap2, b0); ffma2(acc[2][1], ap2, b1); ffma2(acc[2][2], ap2, b2); ffma2(acc[2][3], ap2, b3);
        ffma2(acc[3][0], ap3, b0); ffma2(acc[3][1], ap3, b1); ffma2(acc[3][2], ap3, b2); ffma2(acc[3][3], ap3, b3);
    }
}

// layer over row-major tile sIn[64][RMP]: 8 broadcast scalar loads + packs
__device__ __forceinline__ void gemm_layer_rm(const float* __restrict__ sIn,
                                              const float* __restrict__ sW,
                                              int rb, int tc, ull acc[4][4]) {
    const float* base = sIn + rb*RMP;
    #pragma unroll 2
    for (int k = 0; k < 128; k++) {
        float h0 = base[0*RMP + k], h1 = base[1*RMP + k];
        float h2 = base[2*RMP + k], h3 = base[3*RMP + k];
        float h4 = base[4*RMP + k], h5 = base[5*RMP + k];
        float h6 = base[6*RMP + k], h7 = base[7*RMP + k];
        ull ap0 = pack2f(h0, h1), ap1 = pack2f(h2, h3);
        ull ap2 = pack2f(h4, h5), ap3 = pack2f(h6, h7);
        float4 bv = *(const float4*)(sW + k*128 + tc*4);
        ull b0 = bcast2(bv.x), b1 = bcast2(bv.y), b2 = bcast2(bv.z), b3 = bcast2(bv.w);
        ffma2(acc[0][0], ap0, b0); ffma2(acc[0][1], ap0, b1); ffma2(acc[0][2], ap0, b2); ffma2(acc[0][3], ap0, b3);
        ffma2(acc[1][0], ap1, b0); ffma2(acc[1][1], ap1, b1); ffma2(acc[1][2], ap1, b2); ffma2(acc[1][3], ap1, b3);
        ffma2(acc[2][0], ap2, b0); ffma2(acc[2][1], ap2, b1); ffma2(acc[2][2], ap2, b2); ffma2(acc[2][3], ap2, b3);
        ffma2(acc[3][0], ap3, b0); ffma2(acc[3][1], ap3, b1); ffma2(acc[3][2], ap3, b2); ffma2(acc[3][3], ap3, b3);
    }
}

__device__ __forceinline__ void zero_acc(ull acc[4][4]) {
    #pragma unroll
    for (int p = 0; p < 4; p++)
        #pragma unroll
        for (int c = 0; c < 4; c++) acc[p][c] = 0ull;
}

// bias+relu epilogue -> row-major smem buffer (conflict-free float4 stores)
__device__ __forceinline__ void relu_store_rm(const ull acc[4][4], float4 bv,
                                              float* __restrict__ sOut, int rb, int tc) {
    #pragma unroll
    for (int p = 0; p < 4; p++) {
        float2 v0 = unpack2(acc[p][0]);
        float2 v1 = unpack2(acc[p][1]);
        float2 v2 = unpack2(acc[p][2]);
        float2 v3 = unpack2(acc[p][3]);
        float4 lo, hi;
        lo.x = fmaxf(v0.x + bv.x, 0.f); hi.x = fmaxf(v0.y + bv.x, 0.f);
        lo.y = fmaxf(v1.x + bv.y, 0.f); hi.y = fmaxf(v1.y + bv.y, 0.f);
        lo.z = fmaxf(v2.x + bv.z, 0.f); hi.z = fmaxf(v2.y + bv.z, 0.f);
        lo.w = fmaxf(v3.x + bv.w, 0.f); hi.w = fmaxf(v3.y + bv.w, 0.f);
        *(float4*)&sOut[(rb + 2*p)*RMP + tc*4]     = lo;
        *(float4*)&sOut[(rb + 2*p + 1)*RMP + tc*4] = hi;
    }
}

__device__ __forceinline__ void load_tileT(float* __restrict__ sAT,
                                           const float* __restrict__ A,
                                           int row0, int tid) {
    for (int idx = tid; idx < TILE_R*128; idx += 256) {
        int r = idx >> 7, k = idx & 127;
        int row = row0 + r;
        sAT[k*PAD + r] = (row < NN) ? A[(size_t)row*128 + k] : 0.f;
    }
}

__device__ __forceinline__ void copy_w(float* __restrict__ dst,
                                       const float* __restrict__ src, int tid) {
    const float4* s4 = (const float4*)src;
    float4* d4 = (float4*)dst;
    for (int i = tid; i < 4096; i += 256) d4[i] = s4[i];
}

// ================= fc_x: x_out = x + relu(x@Wf1+bf1)@Wf2 + bf2 =================
#define SMEM_FC_FLOATS (16384 + 16384 + 128*PAD + 64*RMP)
#define SMEM_FC_BYTES  (SMEM_FC_FLOATS * 4)

__global__ __launch_bounds__(256, 1) void fc_x_kernel(
    const float* __restrict__ X,
    const float* __restrict__ W1, const float* __restrict__ B1,
    const float* __restrict__ W2, const float* __restrict__ B2,
    float* __restrict__ OUT)
{
    extern __shared__ float sm[];
    float* sW1 = sm;
    float* sW2 = sm + 16384;
    float* sAT = sm + 32768;            // [128][PAD]
    float* sH  = sm + 32768 + 128*PAD;  // [64][RMP]

    const int tid = threadIdx.x;
    const int tc = tid & 31;
    const int rb = (tid >> 5) * 8;
    const int row0 = blockIdx.x * TILE_R;

    float4 vb1 = ((const float4*)B1)[tc];
    float4 vb2 = ((const float4*)B2)[tc];

    copy_w(sW1, W1, tid);
    copy_w(sW2, W2, tid);
    load_tileT(sAT, X, row0, tid);
    __syncthreads();

    ull acc[4][4];
    zero_acc(acc);
    gemm_layer_T(sAT, sW1, rb, tc, acc);
    relu_store_rm(acc, vb1, sH, rb, tc);
    __syncthreads();

    zero_acc(acc);
    gemm_layer_rm(sH, sW2, rb, tc, acc);

    #pragma unroll
    for (int p = 0; p < 4; p++) {
        float2 v0 = unpack2(acc[p][0]);
        float2 v1 = unpack2(acc[p][1]);
        float2 v2 = unpack2(acc[p][2]);
        float2 v3 = unpack2(acc[p][3]);
        #pragma unroll
        for (int q = 0; q < 2; q++) {
            int row = row0 + rb + 2*p + q;
            if (row < NN) {
                float4 xv = ((const float4*)X)[(size_t)row*32 + tc];
                float4 o;
                o.x = xv.x + (q ? v0.y : v0.x) + vb2.x;
                o.y = xv.y + (q ? v1.y : v1.x) + vb2.y;
                o.z = xv.z + (q ? v2.y : v2.x) + vb2.z;
                o.w = xv.w + (q ? v3.y : v3.x) + vb2.w;
                ((float4*)OUT)[(size_t)row*32 + tc] = o;
            }
        }
    }
}

// ================= fused t-branch =================
// t2 = relu(t + mlp_a(ua) + mlp_b(ub));  t_out = t2 + LN(relu(t2@Wo+bo))*g + b
#define SMEM_T_FLOATS (16384 + 16384 + 128*PAD + 64*RMP)
#define SMEM_T_BYTES  (SMEM_T_FLOATS * 4)

__global__ __launch_bounds__(256, 1) void fused_t_kernel(
    const float* __restrict__ ua, const float* __restrict__ ub,
    const float* __restrict__ t,
    const float* __restrict__ W1a, const float* __restrict__ b1a,
    const float* __restrict__ W2a, const float* __restrict__ b2a,
    const float* __restrict__ W1b, const float* __restrict__ b1b,
    const float* __restrict__ W2b, const float* __restrict__ b2b,
    const float* __restrict__ Wo,  const float* __restrict__ bo,
    const float* __restrict__ lng, const float* __restrict__ lnb,
    float* __restrict__ OUT)
{
    extern __shared__ float sm[];
    float* sW1 = sm;
    float* sW2 = sm + 16384;
    float* sAT = sm + 32768;            // [128][PAD]; reused as z[64][RMP]
    float* sH  = sm + 32768 + 128*PAD;  // [64][RMP]; holds H then t2

    const int tid = threadIdx.x;
    const int tc  = tid & 31;
    const int trg = tid >> 5;
    const int rb  = trg * 8;
    const int row0 = blockIdx.x * TILE_R;

    float4 vb1a = ((const float4*)b1a)[tc];
    float4 vb2a = ((const float4*)b2a)[tc];
    float4 vb1b = ((const float4*)b1b)[tc];
    float4 vb2b = ((const float4*)b2b)[tc];
    float4 vbo  = ((const float4*)bo)[tc];
    float4 vg   = ((const float4*)lng)[tc];
    float4 vbe  = ((const float4*)lnb)[tc];

    // ---- phase A: gin_a(ua) ----
    copy_w(sW1, W1a, tid);
    copy_w(sW2, W2a, tid);
    load_tileT(sAT, ua, row0, tid);
    __syncthreads();

    ull acc[4][4], ga[4][4];
    zero_acc(acc);
    gemm_layer_T(sAT, sW1, rb, tc, acc);
    relu_store_rm(acc, vb1a, sH, rb, tc);
    __syncthreads();

    zero_acc(ga);
    gemm_layer_rm(sH, sW2, rb, tc, ga);
    __syncthreads();                       // done with sW*, sAT, sH

    // ---- phase B: gin_b(ub) ----
    copy_w(sW1, W1b, tid);
    copy_w(sW2, W2b, tid);
    load_tileT(sAT, ub, row0, tid);
    __syncthreads();

    zero_acc(acc);
    gemm_layer_T(sAT, sW1, rb, tc, acc);
    relu_store_rm(acc, vb1b, sH, rb, tc);
    __syncthreads();

    zero_acc(acc);
    gemm_layer_rm(sH, sW2, rb, tc, acc);
    __syncthreads();                       // before overwriting sH with t2

    // ---- t2 = relu(t + ga+b2a + acc+b2b) -> sH (row-major) ----
    #pragma unroll
    for (int p = 0; p < 4; p++) {
        float2 a0 = unpack2(ga[p][0]),  a1 = unpack2(ga[p][1]);
        float2 a2 = unpack2(ga[p][2]),  a3 = unpack2(ga[p][3]);
        float2 c0 = unpack2(acc[p][0]), c1 = unpack2(acc[p][1]);
        float2 c2 = unpack2(acc[p][2]), c3 = unpack2(acc[p][3]);
        #pragma unroll
        for (int q = 0; q < 2; q++) {
            int r = rb + 2*p + q;
            int row = row0 + r;
            float4 tv = make_float4(0.f, 0.f, 0.f, 0.f);
            if (row < NN) tv = ((const float4*)t)[(size_t)row*32 + tc];
            float4 o;
            o.x = fmaxf(tv.x + (q ? a0.y : a0.x) + vb2a.x + (q ? c0.y : c0.x) + vb2b.x, 0.f);
            o.y = fmaxf(tv.y + (q ? a1.y : a1.x) + vb2a.y + (q ? c1.y : c1.x) + vb2b.y, 0.f);
            o.z = fmaxf(tv.z + (q ? a2.y : a2.x) + vb2a.z + (q ? c2.y : c2.x) + vb2b.z, 0.f);
            o.w = fmaxf(tv.w + (q ? a3.y : a3.x) + vb2a.w + (q ? c3.y : c3.x) + vb2b.w, 0.f);
            *(float4*)&sH[r*RMP + tc*4] = o;
        }
    }
    __syncthreads();

    // ---- phase O: z = relu(t2@Wo + bo) -> sZ (reuse sAT region) ----
    copy_w(sW1, Wo, tid);
    __syncthreads();

    zero_acc(acc);
    gemm_layer_rm(sH, sW1, rb, tc, acc);

    float* sZ = sAT;
    relu_store_rm(acc, vbo, sZ, rb, tc);
    __syncthreads();

    // ---- LayerNorm + residual: warp per row ----
    #pragma unroll
    for (int rr = 0; rr < 8; rr++) {
        int r = rr*8 + trg;
        int row = row0 + r;
        float4 z = *(const float4*)&sZ[r*RMP + tc*4];
        float s  = z.x + z.y + z.z + z.w;
        float sq = z.x*z.x + z.y*z.y + z.z*z.z + z.w*z.w;
        #pragma unroll
        for (int d = 16; d > 0; d >>= 1) {
            s  += __shfl_xor_sync(0xffffffffu, s,  d);
            sq += __shfl_xor_sync(0xffffffffu, sq, d);
        }
        float m = s * (1.f/128.f);
        float var = sq * (1.f/128.f) - m*m;
        float rstd = rsqrtf(var + 1e-5f);
        if (row < NN) {
            float4 t2v = *(const float4*)&sH[r*RMP + tc*4];
            float4 o;
            o.x = t2v.x + (z.x - m)*rstd*vg.x + vbe.x;
            o.y = t2v.y + (z.y - m)*rstd*vg.y + vbe.y;
            o.z = t2v.z + (z.z - m)*rstd*vg.z + vbe.z;
            o.w = t2v.w + (z.w - m)*rstd*vg.w + vbe.w;
            ((float4*)OUT)[(size_t)row*32 + tc] = o;
        }
    }
}

// ---------------- launcher ----------------
extern "C" void kernel_launch(void* const* d_in, const int* in_sizes, int n_in,
                              void* d_out, int out_size) {
    const float* x   = (const float*)d_in[0];
    const float* t   = (const float*)d_in[1];
    const int*   et  = (const int*)d_in[2];
    const int*   ex  = (const int*)d_in[3];
    const float* W1a = (const float*)d_in[4];
    const float* b1a = (const float*)d_in[5];
    const float* W2a = (const float*)d_in[6];
    const float* b2a = (const float*)d_in[7];
    const float* W1b = (const float*)d_in[8];
    const float* b1b = (const float*)d_in[9];
    const float* W2b = (const float*)d_in[10];
    const float* b2b = (const float*)d_in[11];
    const float* Wo  = (const float*)d_in[12];
    const float* bo  = (const float*)d_in[13];
    const float* lng = (const float*)d_in[14];
    const float* lnb = (const float*)d_in[15];
    const float* Wf1 = (const float*)d_in[16];
    const float* bf1 = (const float*)d_in[17];
    const float* Wf2 = (const float*)d_in[18];
    const float* bf2 = (const float*)d_in[19];
    float* out = (float*)d_out;

    float *pua, *pub;
    cudaGetSymbolAddress((void**)&pua, g_ua);
    cudaGetSymbolAddress((void**)&pub, g_ub);

    cudaFuncSetAttribute(fc_x_kernel, cudaFuncAttributeMaxDynamicSharedMemorySize, SMEM_FC_BYTES);
    cudaFuncSetAttribute(fused_t_kernel, cudaFuncAttributeMaxDynamicSharedMemorySize, SMEM_T_BYTES);

    // CSR build (fc_x placed 4th so the ncu capture lands on a GEMM kernel)
    zero_cnt_kernel<<<(TWO_N + 1023)/1024, 1024>>>();
    hist_kernel<<<(EE + 255)/256, 256>>>(et, ex);
    scan1_kernel<<<NSB, SCAN_B>>>();
    fc_x_kernel<<<NBLK, 256, SMEM_FC_BYTES>>>(x, Wf1, bf1, Wf2, bf2, out);
    scan2_kernel<<<1, 256>>>();
    scan3_kernel<<<(TWO_N + 1 + 255)/256, 256>>>();
    fill_kernel<<<(EE + 255)/256, 256>>>(et, ex);

    // aggregate: ua = t + sum t[src] (e_t), ub = t + sum x[src] (e_xct)
    agg_kernel<<<(NN + 7)/8, 256>>>(x, t, pua, pub);

    // fused t-branch: gin_a + gin_b + t2 + out Linear + LayerNorm + residual
    fused_t_kernel<<<NBLK, 256, SMEM_T_BYTES>>>(pua, pub, t,
        W1a, b1a, W2a, b2a, W1b, b1b, W2b, b2b,
        Wo, bo, lng, lnb, out + (size_t)NN*DD);
}

// round 4
// speedup vs baseline: 1.2622x; 1.2622x over previous
#include <cuda_runtime.h>

typedef unsigned long long ull;

#define NN 50000
#define DD 128
#define EE 1600000
#define TWO_N (2*NN)
#define SCAN_B 512
#define NSB ((TWO_N + SCAN_B - 1)/SCAN_B)
#define TILE_R 64
#define NBLK ((NN + TILE_R - 1)/TILE_R)
#define PAD 68     // transposed tile pad (words), multiple of 4 for b64x2 loads
#define RMP 132    // row-major pad
#define GT 512     // GEMM kernel threads

// ---------------- f32x2 packed-math helpers ----------------
__device__ __forceinline__ ull bcast2(float x) {
    ull r; asm("mov.b64 %0, {%1,%1};" : "=l"(r) : "f"(x)); return r;
}
__device__ __forceinline__ ull pack2f(float lo, float hi) {
    ull r; asm("mov.b64 %0, {%1,%2};" : "=l"(r) : "f"(lo), "f"(hi)); return r;
}
__device__ __forceinline__ void ffma2(ull& d, ull a, ull b) {
    asm("fma.rn.f32x2 %0, %1, %2, %0;" : "+l"(d) : "l"(a), "l"(b));
}
__device__ __forceinline__ float2 unpack2(ull v) {
    float2 f; asm("mov.b64 {%0,%1}, %2;" : "=f"(f.x), "=f"(f.y) : "l"(v)); return f;
}

// ---------------- scratch ----------------
__device__ int   g_cnt[TWO_N];
__device__ int   g_off[TWO_N + 1];
__device__ int   g_bsum[NSB];
__device__ int   g_col[2*EE];
__device__ float g_ua[NN*DD];
__device__ float g_ub[NN*DD];

// ---------------- CSR construction ----------------
__global__ void zero_cnt_kernel() {
    int i = blockIdx.x*blockDim.x + threadIdx.x;
    if (i < TWO_N) g_cnt[i] = 0;
}

__global__ void hist_kernel(const int* __restrict__ et, const int* __restrict__ ex) {
    int i = blockIdx.x*blockDim.x + threadIdx.x;
    if (i < EE) {
        atomicAdd(&g_cnt[et[EE + i]], 1);
        atomicAdd(&g_cnt[NN + ex[EE + i]], 1);
    }
}

__global__ void scan1_kernel() {
    __shared__ int s[SCAN_B];
    int i = blockIdx.x*SCAN_B + threadIdx.x;
    int v = (i < TWO_N) ? g_cnt[i] : 0;
    s[threadIdx.x] = v;
    __syncthreads();
    #pragma unroll
    for (int d = 1; d < SCAN_B; d <<= 1) {
        int tv = (threadIdx.x >= d) ? s[threadIdx.x - d] : 0;
        __syncthreads();
        s[threadIdx.x] += tv;
        __syncthreads();
    }
    if (i < TWO_N) g_off[i + 1] = s[threadIdx.x];
    if (threadIdx.x == SCAN_B - 1) g_bsum[blockIdx.x] = s[SCAN_B - 1];
}

__global__ void scan2_kernel() {
    __shared__ int s[256];
    int v = (threadIdx.x < NSB) ? g_bsum[threadIdx.x] : 0;
    s[threadIdx.x] = v;
    __syncthreads();
    #pragma unroll
    for (int d = 1; d < 256; d <<= 1) {
        int tv = (threadIdx.x >= d) ? s[threadIdx.x - d] : 0;
        __syncthreads();
        s[threadIdx.x] += tv;
        __syncthreads();
    }
    if (threadIdx.x < NSB) g_bsum[threadIdx.x] = s[threadIdx.x] - v;
}

__global__ void scan3_kernel() {
    int i = blockIdx.x*blockDim.x + threadIdx.x;
    if (i == 0) { g_off[0] = 0; g_cnt[0] = 0; }
    else if (i <= TWO_N) {
        int v = g_off[i] + g_bsum[(i - 1) / SCAN_B];
        g_off[i] = v;
        if (i < TWO_N) g_cnt[i] = v;
    }
}

__global__ void fill_kernel(const int* __restrict__ et, const int* __restrict__ ex) {
    int i = blockIdx.x*blockDim.x + threadIdx.x;
    if (i < EE) {
        int p = atomicAdd(&g_cnt[et[EE + i]], 1);
        g_col[p] = et[i];
        int q = atomicAdd(&g_cnt[NN + ex[EE + i]], 1);
        g_col[q] = ex[i];
    }
}

// ---------------- aggregation: warp per destination node ----------------
__global__ void agg_kernel(const float* __restrict__ x, const float* __restrict__ t,
                           float* __restrict__ ua, float* __restrict__ ub) {
    int warp = (blockIdx.x*blockDim.x + threadIdx.x) >> 5;
    int lane = threadIdx.x & 31;
    if (warp >= NN) return;
    const float4* t4 = (const float4*)t;
    const float4* x4 = (const float4*)x;

    float4 base = t4[warp*32 + lane];
    float4 aA = base, aB = base;

    int e  = g_off[warp],      eE = g_off[warp + 1];
    for (; e + 1 < eE; e += 2) {
        int s0 = g_col[e], s1 = g_col[e + 1];
        float4 v0 = t4[s0*32 + lane];
        float4 v1 = t4[s1*32 + lane];
        aA.x += v0.x; aA.y += v0.y; aA.z += v0.z; aA.w += v0.w;
        aA.x += v1.x; aA.y += v1.y; aA.z += v1.z; aA.w += v1.w;
    }
    if (e < eE) {
        int s0 = g_col[e];
        float4 v0 = t4[s0*32 + lane];
        aA.x += v0.x; aA.y += v0.y; aA.z += v0.z; aA.w += v0.w;
    }

    e = g_off[NN + warp]; eE = g_off[NN + warp + 1];
    for (; e + 1 < eE; e += 2) {
        int s0 = g_col[e], s1 = g_col[e + 1];
        float4 v0 = x4[s0*32 + lane];
        float4 v1 = x4[s1*32 + lane];
        aB.x += v0.x; aB.y += v0.y; aB.z += v0.z; aB.w += v0.w;
        aB.x += v1.x; aB.y += v1.y; aB.z += v1.z; aB.w += v1.w;
    }
    if (e < eE) {
        int s0 = g_col[e];
        float4 v0 = x4[s0*32 + lane];
        aB.x += v0.x; aB.y += v0.y; aB.z += v0.z; aB.w += v0.w;
    }

    ((float4*)ua)[warp*32 + lane] = aA;
    ((float4*)ub)[warp*32 + lane] = aB;
}

// ================= GEMM building blocks (512 threads: 4 rows x 4 cols each) ====
// layer over transposed tile sIn[128][PAD]: one aligned b64x2 load = 4 rows
__device__ __forceinline__ void gemm_layer_T(const float* __restrict__ sIn,
                                             const float* __restrict__ sW,
                                             int rb, int tc, ull acc[2][4]) {
    #pragma unroll 4
    for (int k = 0; k < 128; k++) {
        ulonglong2 A0 = *(const ulonglong2*)&sIn[k*PAD + rb];   // rows rb..rb+3
        float4 bv = *(const float4*)(sW + k*128 + tc*4);
        ull b0 = bcast2(bv.x), b1 = bcast2(bv.y), b2 = bcast2(bv.z), b3 = bcast2(bv.w);
        ull ap0 = A0.x, ap1 = A0.y;
        ffma2(acc[0][0], ap0, b0); ffma2(acc[0][1], ap0, b1); ffma2(acc[0][2], ap0, b2); ffma2(acc[0][3], ap0, b3);
        ffma2(acc[1][0], ap1, b0); ffma2(acc[1][1], ap1, b1); ffma2(acc[1][2], ap1, b2); ffma2(acc[1][3], ap1, b3);
    }
}

// layer over row-major tile sIn[64][RMP]: 4 broadcast scalar loads + packs
__device__ __forceinline__ void gemm_layer_rm(const float* __restrict__ sIn,
                                              const float* __restrict__ sW,
                                              int rb, int tc, ull acc[2][4]) {
    const float* base = sIn + rb*RMP;
    #pragma unroll 4
    for (int k = 0; k < 128; k++) {
        float h0 = base[0*RMP + k], h1 = base[1*RMP + k];
        float h2 = base[2*RMP + k], h3 = base[3*RMP + k];
        ull ap0 = pack2f(h0, h1), ap1 = pack2f(h2, h3);
        float4 bv = *(const float4*)(sW + k*128 + tc*4);
        ull b0 = bcast2(bv.x), b1 = bcast2(bv.y), b2 = bcast2(bv.z), b3 = bcast2(bv.w);
        ffma2(acc[0][0], ap0, b0); ffma2(acc[0][1], ap0, b1); ffma2(acc[0][2], ap0, b2); ffma2(acc[0][3], ap0, b3);
        ffma2(acc[1][0], ap1, b0); ffma2(acc[1][1], ap1, b1); ffma2(acc[1][2], ap1, b2); ffma2(acc[1][3], ap1, b3);
    }
}

__device__ __forceinline__ void zero_acc(ull acc[2][4]) {
    #pragma unroll
    for (int p = 0; p < 2; p++)
        #pragma unroll
        for (int c = 0; c < 4; c++) acc[p][c] = 0ull;
}

// bias+relu epilogue -> row-major smem buffer (conflict-free float4 stores)
__device__ __forceinline__ void relu_store_rm(const ull acc[2][4], float4 bv,
                                              float* __restrict__ sOut, int rb, int tc) {
    #pragma unroll
    for (int p = 0; p < 2; p++) {
        float2 v0 = unpack2(acc[p][0]);
        float2 v1 = unpack2(acc[p][1]);
        float2 v2 = unpack2(acc[p][2]);
        float2 v3 = unpack2(acc[p][3]);
        float4 lo, hi;
        lo.x = fmaxf(v0.x + bv.x, 0.f); hi.x = fmaxf(v0.y + bv.x, 0.f);
        lo.y = fmaxf(v1.x + bv.y, 0.f); hi.y = fmaxf(v1.y + bv.y, 0.f);
        lo.z = fmaxf(v2.x + bv.z, 0.f); hi.z = fmaxf(v2.y + bv.z, 0.f);
        lo.w = fmaxf(v3.x + bv.w, 0.f); hi.w = fmaxf(v3.y + bv.w, 0.f);
        *(float4*)&sOut[(rb + 2*p)*RMP + tc*4]     = lo;
        *(float4*)&sOut[(rb + 2*p + 1)*RMP + tc*4] = hi;
    }
}

__device__ __forceinline__ void load_tileT(float* __restrict__ sAT,
                                           const float* __restrict__ A,
                                           int row0, int tid) {
    #pragma unroll
    for (int idx = tid; idx < TILE_R*128; idx += GT) {
        int r = idx >> 7, k = idx & 127;
        int row = row0 + r;
        sAT[k*PAD + r] = (row < NN) ? A[(size_t)row*128 + k] : 0.f;
    }
}

__device__ __forceinline__ void copy_w(float* __restrict__ dst,
                                       const float* __restrict__ src, int tid) {
    const float4* s4 = (const float4*)src;
    float4* d4 = (float4*)dst;
    #pragma unroll
    for (int i = tid; i < 4096; i += GT) d4[i] = s4[i];
}

// ================= fc_x: x_out = x + relu(x@Wf1+bf1)@Wf2 + bf2 =================
#define SMEM_FC_FLOATS (16384 + 16384 + 128*PAD + 64*RMP)
#define SMEM_FC_BYTES  (SMEM_FC_FLOATS * 4)

__global__ __launch_bounds__(GT, 1) void fc_x_kernel(
    const float* __restrict__ X,
    const float* __restrict__ W1, const float* __restrict__ B1,
    const float* __restrict__ W2, const float* __restrict__ B2,
    float* __restrict__ OUT)
{
    extern __shared__ float sm[];
    float* sW1 = sm;
    float* sW2 = sm + 16384;
    float* sAT = sm + 32768;            // [128][PAD]
    float* sH  = sm + 32768 + 128*PAD;  // [64][RMP]

    const int tid = threadIdx.x;
    const int tc = tid & 31;
    const int rb = (tid >> 5) * 4;      // 16 warps * 4 rows = 64
    const int row0 = blockIdx.x * TILE_R;

    float4 vb1 = ((const float4*)B1)[tc];
    float4 vb2 = ((const float4*)B2)[tc];

    copy_w(sW1, W1, tid);
    copy_w(sW2, W2, tid);
    load_tileT(sAT, X, row0, tid);
    __syncthreads();

    ull acc[2][4];
    zero_acc(acc);
    gemm_layer_T(sAT, sW1, rb, tc, acc);
    relu_store_rm(acc, vb1, sH, rb, tc);
    __syncthreads();

    zero_acc(acc);
    gemm_layer_rm(sH, sW2, rb, tc, acc);

    #pragma unroll
    for (int p = 0; p < 2; p++) {
        float2 v0 = unpack2(acc[p][0]);
        float2 v1 = unpack2(acc[p][1]);
        float2 v2 = unpack2(acc[p][2]);
        float2 v3 = unpack2(acc[p][3]);
        #pragma unroll
        for (int q = 0; q < 2; q++) {
            int row = row0 + rb + 2*p + q;
            if (row < NN) {
                float4 xv = ((const float4*)X)[(size_t)row*32 + tc];
                float4 o;
                o.x = xv.x + (q ? v0.y : v0.x) + vb2.x;
                o.y = xv.y + (q ? v1.y : v1.x) + vb2.y;
                o.z = xv.z + (q ? v2.y : v2.x) + vb2.z;
                o.w = xv.w + (q ? v3.y : v3.x) + vb2.w;
                ((float4*)OUT)[(size_t)row*32 + tc] = o;
            }
        }
    }
}

// ================= fused t-branch =================
// t2 = relu(t + mlp_a(ua) + mlp_b(ub));  t_out = t2 + LN(relu(t2@Wo+bo))*g + b
#define SMEM_T_FLOATS (16384 + 16384 + 128*PAD + 64*RMP)
#define SMEM_T_BYTES  (SMEM_T_FLOATS * 4)

__global__ __launch_bounds__(GT, 1) void fused_t_kernel(
    const float* __restrict__ ua, const float* __restrict__ ub,
    const float* __restrict__ t,
    const float* __restrict__ W1a, const float* __restrict__ b1a,
    const float* __restrict__ W2a, const float* __restrict__ b2a,
    const float* __restrict__ W1b, const float* __restrict__ b1b,
    const float* __restrict__ W2b, const float* __restrict__ b2b,
    const float* __restrict__ Wo,  const float* __restrict__ bo,
    const float* __restrict__ lng, const float* __restrict__ lnb,
    float* __restrict__ OUT)
{
    extern __shared__ float sm[];
    float* sW1 = sm;
    float* sW2 = sm + 16384;
    float* sAT = sm + 32768;            // [128][PAD]; reused as z[64][RMP]
    float* sH  = sm + 32768 + 128*PAD;  // [64][RMP]; holds H then t2

    const int tid = threadIdx.x;
    const int tc  = tid & 31;
    const int trg = tid >> 5;           // 0..15
    const int rb  = trg * 4;
    const int row0 = blockIdx.x * TILE_R;

    float4 vb1a = ((const float4*)b1a)[tc];
    float4 vb2a = ((const float4*)b2a)[tc];
    float4 vb1b = ((const float4*)b1b)[tc];
    float4 vb2b = ((const float4*)b2b)[tc];
    float4 vbo  = ((const float4*)bo)[tc];
    float4 vg   = ((const float4*)lng)[tc];
    float4 vbe  = ((const float4*)lnb)[tc];

    // ---- phase A: gin_a(ua) ----
    copy_w(sW1, W1a, tid);
    copy_w(sW2, W2a, tid);
    load_tileT(sAT, ua, row0, tid);
    __syncthreads();

    ull acc[2][4], ga[2][4];
    zero_acc(acc);
    gemm_layer_T(sAT, sW1, rb, tc, acc);
    relu_store_rm(acc, vb1a, sH, rb, tc);
    __syncthreads();

    zero_acc(ga);
    gemm_layer_rm(sH, sW2, rb, tc, ga);
    __syncthreads();                       // done with sW*, sAT, sH

    // ---- phase B: gin_b(ub) ----
    copy_w(sW1, W1b, tid);
    copy_w(sW2, W2b, tid);
    load_tileT(sAT, ub, row0, tid);
    __syncthreads();

    zero_acc(acc);
    gemm_layer_T(sAT, sW1, rb, tc, acc);
    relu_store_rm(acc, vb1b, sH, rb, tc);
    __syncthreads();

    zero_acc(acc);
    gemm_layer_rm(sH, sW2, rb, tc, acc);
    __syncthreads();                       // before overwriting sH with t2

    // ---- t2 = relu(t + ga+b2a + acc+b2b) -> sH (row-major) ----
    #pragma unroll
    for (int p = 0; p < 2; p++) {
        float2 a0 = unpack2(ga[p][0]),  a1 = unpack2(ga[p][1]);
        float2 a2 = unpack2(ga[p][2]),  a3 = unpack2(ga[p][3]);
        float2 c0 = unpack2(acc[p][0]), c1 = unpack2(acc[p][1]);
        float2 c2 = unpack2(acc[p][2]), c3 = unpack2(acc[p][3]);
        #pragma unroll
        for (int q = 0; q < 2; q++) {
            int r = rb + 2*p + q;
            int row = row0 + r;
            float4 tv = make_float4(0.f, 0.f, 0.f, 0.f);
            if (row < NN) tv = ((const float4*)t)[(size_t)row*32 + tc];
            float4 o;
            o.x = fmaxf(tv.x + (q ? a0.y : a0.x) + vb2a.x + (q ? c0.y : c0.x) + vb2b.x, 0.f);
            o.y = fmaxf(tv.y + (q ? a1.y : a1.x) + vb2a.y + (q ? c1.y : c1.x) + vb2b.y, 0.f);
            o.z = fmaxf(tv.z + (q ? a2.y : a2.x) + vb2a.z + (q ? c2.y : c2.x) + vb2b.z, 0.f);
            o.w = fmaxf(tv.w + (q ? a3.y : a3.x) + vb2a.w + (q ? c3.y : c3.x) + vb2b.w, 0.f);
            *(float4*)&sH[r*RMP + tc*4] = o;
        }
    }
    __syncthreads();

    // ---- phase O: z = relu(t2@Wo + bo) -> sZ (reuse sAT region) ----
    copy_w(sW1, Wo, tid);
    __syncthreads();

    zero_acc(acc);
    gemm_layer_rm(sH, sW1, rb, tc, acc);

    float* sZ = sAT;
    relu_store_rm(acc, vbo, sZ, rb, tc);
    __syncthreads();

    // ---- LayerNorm + residual: warp per row, 4 rows per warp ----
    #pragma unroll
    for (int rr = 0; rr < 4; rr++) {
        int r = rr*16 + trg;
        int row = row0 + r;
        float4 z = *(const float4*)&sZ[r*RMP + tc*4];
        float s  = z.x + z.y + z.z + z.w;
        float sq = z.x*z.x + z.y*z.y + z.z*z.z + z.w*z.w;
        #pragma unroll
        for (int d = 16; d > 0; d >>= 1) {
            s  += __shfl_xor_sync(0xffffffffu, s,  d);
            sq += __shfl_xor_sync(0xffffffffu, sq, d);
        }
        float m = s * (1.f/128.f);
        float var = sq * (1.f/128.f) - m*m;
        float rstd = rsqrtf(var + 1e-5f);
        if (row < NN) {
            float4 t2v = *(const float4*)&sH[r*RMP + tc*4];
            float4 o;
            o.x = t2v.x + (z.x - m)*rstd*vg.x + vbe.x;
            o.y = t2v.y + (z.y - m)*rstd*vg.y + vbe.y;
            o.z = t2v.z + (z.z - m)*rstd*vg.z + vbe.z;
            o.w = t2v.w + (z.w - m)*rstd*vg.w + vbe.w;
            ((float4*)OUT)[(size_t)row*32 + tc] = o;
        }
    }
}

// ---------------- launcher ----------------
extern "C" void kernel_launch(void* const* d_in, const int* in_sizes, int n_in,
                              void* d_out, int out_size) {
    const float* x   = (const float*)d_in[0];
    const float* t   = (const float*)d_in[1];
    const int*   et  = (const int*)d_in[2];
    const int*   ex  = (const int*)d_in[3];
    const float* W1a = (const float*)d_in[4];
    const float* b1a = (const float*)d_in[5];
    const float* W2a = (const float*)d_in[6];
    const float* b2a = (const float*)d_in[7];
    const float* W1b = (const float*)d_in[8];
    const float* b1b = (const float*)d_in[9];
    const float* W2b = (const float*)d_in[10];
    const float* b2b = (const float*)d_in[11];
    const float* Wo  = (const float*)d_in[12];
    const float* bo  = (const float*)d_in[13];
    const float* lng = (const float*)d_in[14];
    const float* lnb = (const float*)d_in[15];
    const float* Wf1 = (const float*)d_in[16];
    const float* bf1 = (const float*)d_in[17];
    const float* Wf2 = (const float*)d_in[18];
    const float* bf2 = (const float*)d_in[19];
    float* out = (float*)d_out;

    float *pua, *pub;
    cudaGetSymbolAddress((void**)&pua, g_ua);
    cudaGetSymbolAddress((void**)&pub, g_ub);

    cudaFuncSetAttribute(fc_x_kernel, cudaFuncAttributeMaxDynamicSharedMemorySize, SMEM_FC_BYTES);
    cudaFuncSetAttribute(fused_t_kernel, cudaFuncAttributeMaxDynamicSharedMemorySize, SMEM_T_BYTES);

    // CSR build (fc_x placed 4th so the ncu capture lands on a GEMM kernel)
    zero_cnt_kernel<<<(TWO_N + 1023)/1024, 1024>>>();
    hist_kernel<<<(EE + 255)/256, 256>>>(et, ex);
    scan1_kernel<<<NSB, SCAN_B>>>();
    fc_x_kernel<<<NBLK, GT, SMEM_FC_BYTES>>>(x, Wf1, bf1, Wf2, bf2, out);
    scan2_kernel<<<1, 256>>>();
    scan3_kernel<<<(TWO_N + 1 + 255)/256, 256>>>();
    fill_kernel<<<(EE + 255)/256, 256>>>(et, ex);

    // aggregate: ua = t + sum t[src] (e_t), ub = t + sum x[src] (e_xct)
    agg_kernel<<<(NN + 7)/8, 256>>>(x, t, pua, pub);

    // fused t-branch: gin_a + gin_b + t2 + out Linear + LayerNorm + residual
    fused_t_kernel<<<NBLK, GT, SMEM_T_BYTES>>>(pua, pub, t,
        W1a, b1a, W2a, b2a, W1b, b1b, W2b, b2b,
        Wo, bo, lng, lnb, out + (size_t)NN*DD);
}

// round 5
// speedup vs baseline: 1.2847x; 1.0178x over previous
#include <cuda_runtime.h>

typedef unsigned long long ull;

#define NN 50000
#define DD 128
#define EE 1600000
#define TWO_N (2*NN)
#define SCAN_B 512
#define NSB ((TWO_N + SCAN_B - 1)/SCAN_B)
#define TILE_R 32
#define NBLK ((NN + TILE_R - 1)/TILE_R)
#define PAD 36     // transposed tile pad (words), multiple of 4 for b64x2 loads
#define RMP 132    // row-major pad
#define GT 256     // GEMM kernel threads (8 warps)

// ---------------- f32x2 packed-math helpers ----------------
__device__ __forceinline__ ull bcast2(float x) {
    ull r; asm("mov.b64 %0, {%1,%1};" : "=l"(r) : "f"(x)); return r;
}
__device__ __forceinline__ ull pack2f(float lo, float hi) {
    ull r; asm("mov.b64 %0, {%1,%2};" : "=l"(r) : "f"(lo), "f"(hi)); return r;
}
__device__ __forceinline__ void ffma2(ull& d, ull a, ull b) {
    asm("fma.rn.f32x2 %0, %1, %2, %0;" : "+l"(d) : "l"(a), "l"(b));
}
__device__ __forceinline__ float2 unpack2(ull v) {
    float2 f; asm("mov.b64 {%0,%1}, %2;" : "=f"(f.x), "=f"(f.y) : "l"(v)); return f;
}

// ---------------- scratch ----------------
__device__ int   g_cnt[TWO_N];
__device__ int   g_off[TWO_N + 1];
__device__ int   g_bsum[NSB];
__device__ int   g_col[2*EE];
__device__ float g_ua[NN*DD];
__device__ float g_ub[NN*DD];

// ---------------- CSR construction ----------------
__global__ void zero_cnt_kernel() {
    int i = blockIdx.x*blockDim.x + threadIdx.x;
    if (i < TWO_N) g_cnt[i] = 0;
}

__global__ void hist_kernel(const int* __restrict__ et, const int* __restrict__ ex) {
    int i = blockIdx.x*blockDim.x + threadIdx.x;
    if (i < EE) {
        atomicAdd(&g_cnt[et[EE + i]], 1);
        atomicAdd(&g_cnt[NN + ex[EE + i]], 1);
    }
}

__global__ void scan1_kernel() {
    __shared__ int s[SCAN_B];
    int i = blockIdx.x*SCAN_B + threadIdx.x;
    int v = (i < TWO_N) ? g_cnt[i] : 0;
    s[threadIdx.x] = v;
    __syncthreads();
    #pragma unroll
    for (int d = 1; d < SCAN_B; d <<= 1) {
        int tv = (threadIdx.x >= d) ? s[threadIdx.x - d] : 0;
        __syncthreads();
        s[threadIdx.x] += tv;
        __syncthreads();
    }
    if (i < TWO_N) g_off[i + 1] = s[threadIdx.x];
    if (threadIdx.x == SCAN_B - 1) g_bsum[blockIdx.x] = s[SCAN_B - 1];
}

__global__ void scan2_kernel() {
    __shared__ int s[256];
    int v = (threadIdx.x < NSB) ? g_bsum[threadIdx.x] : 0;
    s[threadIdx.x] = v;
    __syncthreads();
    #pragma unroll
    for (int d = 1; d < 256; d <<= 1) {
        int tv = (threadIdx.x >= d) ? s[threadIdx.x - d] : 0;
        __syncthreads();
        s[threadIdx.x] += tv;
        __syncthreads();
    }
    if (threadIdx.x < NSB) g_bsum[threadIdx.x] = s[threadIdx.x] - v;
}

__global__ void scan3_kernel() {
    int i = blockIdx.x*blockDim.x + threadIdx.x;
    if (i == 0) { g_off[0] = 0; g_cnt[0] = 0; }
    else if (i <= TWO_N) {
        int v = g_off[i] + g_bsum[(i - 1) / SCAN_B];
        g_off[i] = v;
        if (i < TWO_N) g_cnt[i] = v;
    }
}

__global__ void fill_kernel(const int* __restrict__ et, const int* __restrict__ ex) {
    int i = blockIdx.x*blockDim.x + threadIdx.x;
    if (i < EE) {
        int p = atomicAdd(&g_cnt[et[EE + i]], 1);
        g_col[p] = et[i];
        int q = atomicAdd(&g_cnt[NN + ex[EE + i]], 1);
        g_col[q] = ex[i];
    }
}

// ---------------- aggregation: warp per destination node ----------------
__global__ void agg_kernel(const float* __restrict__ x, const float* __restrict__ t,
                           float* __restrict__ ua, float* __restrict__ ub) {
    int warp = (blockIdx.x*blockDim.x + threadIdx.x) >> 5;
    int lane = threadIdx.x & 31;
    if (warp >= NN) return;
    const float4* t4 = (const float4*)t;
    const float4* x4 = (const float4*)x;

    float4 base = t4[warp*32 + lane];
    float4 aA = base, aB = base;

    int e  = g_off[warp],      eE = g_off[warp + 1];
    for (; e + 1 < eE; e += 2) {
        int s0 = g_col[e], s1 = g_col[e + 1];
        float4 v0 = t4[s0*32 + lane];
        float4 v1 = t4[s1*32 + lane];
        aA.x += v0.x; aA.y += v0.y; aA.z += v0.z; aA.w += v0.w;
        aA.x += v1.x; aA.y += v1.y; aA.z += v1.z; aA.w += v1.w;
    }
    if (e < eE) {
        int s0 = g_col[e];
        float4 v0 = t4[s0*32 + lane];
        aA.x += v0.x; aA.y += v0.y; aA.z += v0.z; aA.w += v0.w;
    }

    e = g_off[NN + warp]; eE = g_off[NN + warp + 1];
    for (; e + 1 < eE; e += 2) {
        int s0 = g_col[e], s1 = g_col[e + 1];
        float4 v0 = x4[s0*32 + lane];
        float4 v1 = x4[s1*32 + lane];
        aB.x += v0.x; aB.y += v0.y; aB.z += v0.z; aB.w += v0.w;
        aB.x += v1.x; aB.y += v1.y; aB.z += v1.z; aB.w += v1.w;
    }
    if (e < eE) {
        int s0 = g_col[e];
        float4 v0 = x4[s0*32 + lane];
        aB.x += v0.x; aB.y += v0.y; aB.z += v0.z; aB.w += v0.w;
    }

    ((float4*)ua)[warp*32 + lane] = aA;
    ((float4*)ub)[warp*32 + lane] = aB;
}

// ================= GEMM building blocks (256 threads: 4 rows x 4 cols each) ====
// layer over transposed tile sIn[128][PAD]: one aligned b64x2 broadcast load = 4 rows
__device__ __forceinline__ void gemm_layer_T(const float* __restrict__ sIn,
                                             const float* __restrict__ sW,
                                             int rb, int tc, ull acc[2][4]) {
    #pragma unroll 4
    for (int k = 0; k < 128; k++) {
        ulonglong2 A0 = *(const ulonglong2*)&sIn[k*PAD + rb];   // rows rb..rb+3
        float4 bv = *(const float4*)(sW + k*128 + tc*4);
        ull b0 = bcast2(bv.x), b1 = bcast2(bv.y), b2 = bcast2(bv.z), b3 = bcast2(bv.w);
        ull ap0 = A0.x, ap1 = A0.y;
        ffma2(acc[0][0], ap0, b0); ffma2(acc[0][1], ap0, b1); ffma2(acc[0][2], ap0, b2); ffma2(acc[0][3], ap0, b3);
        ffma2(acc[1][0], ap1, b0); ffma2(acc[1][1], ap1, b1); ffma2(acc[1][2], ap1, b2); ffma2(acc[1][3], ap1, b3);
    }
}

// layer over row-major tile sIn[TILE_R][RMP]: 4 broadcast scalar loads + packs
__device__ __forceinline__ void gemm_layer_rm(const float* __restrict__ sIn,
                                              const float* __restrict__ sW,
                                              int rb, int tc, ull acc[2][4]) {
    const float* base = sIn + rb*RMP;
    #pragma unroll 4
    for (int k = 0; k < 128; k++) {
        float h0 = base[0*RMP + k], h1 = base[1*RMP + k];
        float h2 = base[2*RMP + k], h3 = base[3*RMP + k];
        ull ap0 = pack2f(h0, h1), ap1 = pack2f(h2, h3);
        float4 bv = *(const float4*)(sW + k*128 + tc*4);
        ull b0 = bcast2(bv.x), b1 = bcast2(bv.y), b2 = bcast2(bv.z), b3 = bcast2(bv.w);
        ffma2(acc[0][0], ap0, b0); ffma2(acc[0][1], ap0, b1); ffma2(acc[0][2], ap0, b2); ffma2(acc[0][3], ap0, b3);
        ffma2(acc[1][0], ap1, b0); ffma2(acc[1][1], ap1, b1); ffma2(acc[1][2], ap1, b2); ffma2(acc[1][3], ap1, b3);
    }
}

__device__ __forceinline__ void zero_acc(ull acc[2][4]) {
    #pragma unroll
    for (int p = 0; p < 2; p++)
        #pragma unroll
        for (int c = 0; c < 4; c++) acc[p][c] = 0ull;
}

// bias+relu epilogue -> row-major smem buffer (conflict-free float4 stores)
__device__ __forceinline__ void relu_store_rm(const ull acc[2][4], float4 bv,
                                              float* __restrict__ sOut, int rb, int tc) {
    #pragma unroll
    for (int p = 0; p < 2; p++) {
        float2 v0 = unpack2(acc[p][0]);
        float2 v1 = unpack2(acc[p][1]);
        float2 v2 = unpack2(acc[p][2]);
        float2 v3 = unpack2(acc[p][3]);
        float4 lo, hi;
        lo.x = fmaxf(v0.x + bv.x, 0.f); hi.x = fmaxf(v0.y + bv.x, 0.f);
        lo.y = fmaxf(v1.x + bv.y, 0.f); hi.y = fmaxf(v1.y + bv.y, 0.f);
        lo.z = fmaxf(v2.x + bv.z, 0.f); hi.z = fmaxf(v2.y + bv.z, 0.f);
        lo.w = fmaxf(v3.x + bv.w, 0.f); hi.w = fmaxf(v3.y + bv.w, 0.f);
        *(float4*)&sOut[(rb + 2*p)*RMP + tc*4]     = lo;
        *(float4*)&sOut[(rb + 2*p + 1)*RMP + tc*4] = hi;
    }
}

__device__ __forceinline__ void load_tileT(float* __restrict__ sAT,
                                           const float* __restrict__ A,
                                           int row0, int tid) {
    #pragma unroll
    for (int idx = tid; idx < TILE_R*128; idx += GT) {
        int r = idx >> 7, k = idx & 127;
        int row = row0 + r;
        sAT[k*PAD + r] = (row < NN) ? A[(size_t)row*128 + k] : 0.f;
    }
}

__device__ __forceinline__ void copy_w(float* __restrict__ dst,
                                       const float* __restrict__ src, int tid) {
    const float4* s4 = (const float4*)src;
    float4* d4 = (float4*)dst;
    #pragma unroll
    for (int i = tid; i < 4096; i += GT) d4[i] = s4[i];
}

// ================= fc_x: x_out = x + relu(x@Wf1+bf1)@Wf2 + bf2 =================
// smem: sW(16384) + sAT(128*PAD) + sH(TILE_R*RMP)
#define SMEM_FC_FLOATS (16384 + 128*PAD + TILE_R*RMP)
#define SMEM_FC_BYTES  (SMEM_FC_FLOATS * 4)

__global__ __launch_bounds__(GT, 2) void fc_x_kernel(
    const float* __restrict__ X,
    const float* __restrict__ W1, const float* __restrict__ B1,
    const float* __restrict__ W2, const float* __restrict__ B2,
    float* __restrict__ OUT)
{
    extern __shared__ float sm[];
    float* sW  = sm;                    // single staged weight
    float* sAT = sm + 16384;            // [128][PAD]
    float* sH  = sm + 16384 + 128*PAD;  // [TILE_R][RMP]

    const int tid = threadIdx.x;
    const int tc = tid & 31;
    const int rb = (tid >> 5) * 4;      // 8 warps * 4 rows = 32
    const int row0 = blockIdx.x * TILE_R;

    float4 vb1 = ((const float4*)B1)[tc];
    float4 vb2 = ((const float4*)B2)[tc];

    copy_w(sW, W1, tid);
    load_tileT(sAT, X, row0, tid);
    __syncthreads();

    ull acc[2][4];
    zero_acc(acc);
    gemm_layer_T(sAT, sW, rb, tc, acc);
    relu_store_rm(acc, vb1, sH, rb, tc);
    __syncthreads();

    copy_w(sW, W2, tid);
    __syncthreads();

    zero_acc(acc);
    gemm_layer_rm(sH, sW, rb, tc, acc);

    #pragma unroll
    for (int p = 0; p < 2; p++) {
        float2 v0 = unpack2(acc[p][0]);
        float2 v1 = unpack2(acc[p][1]);
        float2 v2 = unpack2(acc[p][2]);
        float2 v3 = unpack2(acc[p][3]);
        #pragma unroll
        for (int q = 0; q < 2; q++) {
            int row = row0 + rb + 2*p + q;
            if (row < NN) {
                float4 xv = ((const float4*)X)[(size_t)row*32 + tc];
                float4 o;
                o.x = xv.x + (q ? v0.y : v0.x) + vb2.x;
                o.y = xv.y + (q ? v1.y : v1.x) + vb2.y;
                o.z = xv.z + (q ? v2.y : v2.x) + vb2.z;
                o.w = xv.w + (q ? v3.y : v3.x) + vb2.w;
                ((float4*)OUT)[(size_t)row*32 + tc] = o;
            }
        }
    }
}

// ================= fused t-branch =================
// t2 = relu(t + mlp_a(ua) + mlp_b(ub));  t_out = t2 + LN(relu(t2@Wo+bo))*g + b
#define SMEM_T_FLOATS (16384 + 128*PAD + TILE_R*RMP)
#define SMEM_T_BYTES  (SMEM_T_FLOATS * 4)

__global__ __launch_bounds__(GT, 2) void fused_t_kernel(
    const float* __restrict__ ua, const float* __restrict__ ub,
    const float* __restrict__ t,
    const float* __restrict__ W1a, const float* __restrict__ b1a,
    const float* __restrict__ W2a, const float* __restrict__ b2a,
    const float* __restrict__ W1b, const float* __restrict__ b1b,
    const float* __restrict__ W2b, const float* __restrict__ b2b,
    const float* __restrict__ Wo,  const float* __restrict__ bo,
    const float* __restrict__ lng, const float* __restrict__ lnb,
    float* __restrict__ OUT)
{
    extern __shared__ float sm[];
    float* sW  = sm;                    // single staged weight
    float* sAT = sm + 16384;            // [128][PAD]; reused as z[TILE_R][RMP]
    float* sH  = sm + 16384 + 128*PAD;  // [TILE_R][RMP]; holds H then t2

    const int tid = threadIdx.x;
    const int tc  = tid & 31;
    const int trg = tid >> 5;           // 0..7
    const int rb  = trg * 4;
    const int row0 = blockIdx.x * TILE_R;

    float4 vb1a = ((const float4*)b1a)[tc];
    float4 vb2a = ((const float4*)b2a)[tc];
    float4 vb1b = ((const float4*)b1b)[tc];
    float4 vb2b = ((const float4*)b2b)[tc];
    float4 vbo  = ((const float4*)bo)[tc];
    float4 vg   = ((const float4*)lng)[tc];
    float4 vbe  = ((const float4*)lnb)[tc];

    // ---- phase A: gin_a(ua) ----
    copy_w(sW, W1a, tid);
    load_tileT(sAT, ua, row0, tid);
    __syncthreads();

    ull acc[2][4], ga[2][4];
    zero_acc(acc);
    gemm_layer_T(sAT, sW, rb, tc, acc);
    relu_store_rm(acc, vb1a, sH, rb, tc);
    __syncthreads();

    copy_w(sW, W2a, tid);
    __syncthreads();

    zero_acc(ga);
    gemm_layer_rm(sH, sW, rb, tc, ga);
    __syncthreads();

    // ---- phase B: gin_b(ub) ----
    copy_w(sW, W1b, tid);
    load_tileT(sAT, ub, row0, tid);
    __syncthreads();

    zero_acc(acc);
    gemm_layer_T(sAT, sW, rb, tc, acc);
    relu_store_rm(acc, vb1b, sH, rb, tc);
    __syncthreads();

    copy_w(sW, W2b, tid);
    __syncthreads();

    zero_acc(acc);
    gemm_layer_rm(sH, sW, rb, tc, acc);
    __syncthreads();                       // before overwriting sH with t2

    // ---- t2 = relu(t + ga+b2a + acc+b2b) -> sH (row-major) ----
    #pragma unroll
    for (int p = 0; p < 2; p++) {
        float2 a0 = unpack2(ga[p][0]),  a1 = unpack2(ga[p][1]);
        float2 a2 = unpack2(ga[p][2]),  a3 = unpack2(ga[p][3]);
        float2 c0 = unpack2(acc[p][0]), c1 = unpack2(acc[p][1]);
        float2 c2 = unpack2(acc[p][2]), c3 = unpack2(acc[p][3]);
        #pragma unroll
        for (int q = 0; q < 2; q++) {
            int r = rb + 2*p + q;
            int row = row0 + r;
            float4 tv = make_float4(0.f, 0.f, 0.f, 0.f);
            if (row < NN) tv = ((const float4*)t)[(size_t)row*32 + tc];
            float4 o;
            o.x = fmaxf(tv.x + (q ? a0.y : a0.x) + vb2a.x + (q ? c0.y : c0.x) + vb2b.x, 0.f);
            o.y = fmaxf(tv.y + (q ? a1.y : a1.x) + vb2a.y + (q ? c1.y : c1.x) + vb2b.y, 0.f);
            o.z = fmaxf(tv.z + (q ? a2.y : a2.x) + vb2a.z + (q ? c2.y : c2.x) + vb2b.z, 0.f);
            o.w = fmaxf(tv.w + (q ? a3.y : a3.x) + vb2a.w + (q ? c3.y : c3.x) + vb2b.w, 0.f);
            *(float4*)&sH[r*RMP + tc*4] = o;
        }
    }
    __syncthreads();

    // ---- phase O: z = relu(t2@Wo + bo) -> sZ (reuse sAT region) ----
    copy_w(sW, Wo, tid);
    __syncthreads();

    zero_acc(acc);
    gemm_layer_rm(sH, sW, rb, tc, acc);

    float* sZ = sAT;
    relu_store_rm(acc, vbo, sZ, rb, tc);
    __syncthreads();

    // ---- LayerNorm + residual: warp per row, 4 rows per warp ----
    #pragma unroll
    for (int rr = 0; rr < 4; rr++) {
        int r = rr*8 + trg;
        int row = row0 + r;
        float4 z = *(const float4*)&sZ[r*RMP + tc*4];
        float s  = z.x + z.y + z.z + z.w;
        float sq = z.x*z.x + z.y*z.y + z.z*z.z + z.w*z.w;
        #pragma unroll
        for (int d = 16; d > 0; d >>= 1) {
            s  += __shfl_xor_sync(0xffffffffu, s,  d);
            sq += __shfl_xor_sync(0xffffffffu, sq, d);
        }
        float m = s * (1.f/128.f);
        float var = sq * (1.f/128.f) - m*m;
        float rstd = rsqrtf(var + 1e-5f);
        if (row < NN) {
            float4 t2v = *(const float4*)&sH[r*RMP + tc*4];
            float4 o;
            o.x = t2v.x + (z.x - m)*rstd*vg.x + vbe.x;
            o.y = t2v.y + (z.y - m)*rstd*vg.y + vbe.y;
            o.z = t2v.z + (z.z - m)*rstd*vg.z + vbe.z;
            o.w = t2v.w + (z.w - m)*rstd*vg.w + vbe.w;
            ((float4*)OUT)[(size_t)row*32 + tc] = o;
        }
    }
}

// ---------------- launcher ----------------
extern "C" void kernel_launch(void* const* d_in, const int* in_sizes, int n_in,
                              void* d_out, int out_size) {
    const float* x   = (const float*)d_in[0];
    const float* t   = (const float*)d_in[1];
    const int*   et  = (const int*)d_in[2];
    const int*   ex  = (const int*)d_in[3];
    const float* W1a = (const float*)d_in[4];
    const float* b1a = (const float*)d_in[5];
    const float* W2a = (const float*)d_in[6];
    const float* b2a = (const float*)d_in[7];
    const float* W1b = (const float*)d_in[8];
    const float* b1b = (const float*)d_in[9];
    const float* W2b = (const float*)d_in[10];
    const float* b2b = (const float*)d_in[11];
    const float* Wo  = (const float*)d_in[12];
    const float* bo  = (const float*)d_in[13];
    const float* lng = (const float*)d_in[14];
    const float* lnb = (const float*)d_in[15];
    const float* Wf1 = (const float*)d_in[16];
    const float* bf1 = (const float*)d_in[17];
    const float* Wf2 = (const float*)d_in[18];
    const float* bf2 = (const float*)d_in[19];
    float* out = (float*)d_out;

    float *pua, *pub;
    cudaGetSymbolAddress((void**)&pua, g_ua);
    cudaGetSymbolAddress((void**)&pub, g_ub);

    cudaFuncSetAttribute(fc_x_kernel, cudaFuncAttributeMaxDynamicSharedMemorySize, SMEM_FC_BYTES);
    cudaFuncSetAttribute(fused_t_kernel, cudaFuncAttributeMaxDynamicSharedMemorySize, SMEM_T_BYTES);

    // CSR build (fc_x placed 4th so the ncu capture lands on a GEMM kernel)
    zero_cnt_kernel<<<(TWO_N + 1023)/1024, 1024>>>();
    hist_kernel<<<(EE + 255)/256, 256>>>(et, ex);
    scan1_kernel<<<NSB, SCAN_B>>>();
    fc_x_kernel<<<NBLK, GT, SMEM_FC_BYTES>>>(x, Wf1, bf1, Wf2, bf2, out);
    scan2_kernel<<<1, 256>>>();
    scan3_kernel<<<(TWO_N + 1 + 255)/256, 256>>>();
    fill_kernel<<<(EE + 255)/256, 256>>>(et, ex);

    // aggregate: ua = t + sum t[src] (e_t), ub = t + sum x[src] (e_xct)
    agg_kernel<<<(NN + 7)/8, 256>>>(x, t, pua, pub);

    // fused t-branch: gin_a + gin_b + t2 + out Linear + LayerNorm + residual
    fused_t_kernel<<<NBLK, GT, SMEM_T_BYTES>>>(pua, pub, t,
        W1a, b1a, W2a, b2a, W1b, b1b, W2b, b2b,
        Wo, bo, lng, lnb, out + (size_t)NN*DD);
}